// round 15
// baseline (speedup 1.0000x reference)
#include <cuda_runtime.h>
#include <math.h>

#define D_MODEL 1024
#define NHEAD   16
#define HD      64
#define BATCH   2
#define SEQ     2048
#define MROWS   (BATCH*SEQ)   // 4096

// Scratch (device globals: allocation-free per harness rules)
__device__ float g_q[MROWS*D_MODEL];
__device__ float g_k[MROWS*D_MODEL];
__device__ float g_v[MROWS*D_MODEL];
__device__ float g_att[MROWS*D_MODEL];

// ---------------------------------------------------------------------------
// Y[m][n] = sum_k X[m][k] * W[n][k] + bias[n]   (torch Linear: x @ W^T + b)
// ---------------------------------------------------------------------------
__global__ __launch_bounds__(256) void sgemm_xwt(
    const float* __restrict__ X, const float* __restrict__ W,
    const float* __restrict__ bias, float* __restrict__ Y,
    int M, int N, int K)
{
    __shared__ float Xs[16][68];   // [k][m]
    __shared__ float Ws[16][68];   // [k][n]

    const int tid = threadIdx.x;
    const int tx  = tid & 15;
    const int ty  = tid >> 4;
    const int bm  = blockIdx.y << 6;
    const int bn  = blockIdx.x << 6;
    const int lrow = tid >> 2;
    const int lk   = (tid & 3) << 2;

    float acc[4][4];
#pragma unroll
    for (int i = 0; i < 4; i++)
#pragma unroll
        for (int j = 0; j < 4; j++) acc[i][j] = 0.f;

    const float* Xp = X + (size_t)(bm + lrow) * K + lk;
    const float* Wp = W + (size_t)(bn + lrow) * K + lk;

    for (int k0 = 0; k0 < K; k0 += 16) {
        float4 xv = *(const float4*)(Xp + k0);
        float4 wv = *(const float4*)(Wp + k0);
        Xs[lk+0][lrow] = xv.x; Xs[lk+1][lrow] = xv.y;
        Xs[lk+2][lrow] = xv.z; Xs[lk+3][lrow] = xv.w;
        Ws[lk+0][lrow] = wv.x; Ws[lk+1][lrow] = wv.y;
        Ws[lk+2][lrow] = wv.z; Ws[lk+3][lrow] = wv.w;
        __syncthreads();
#pragma unroll
        for (int kk = 0; kk < 16; kk++) {
            float4 a = *(const float4*)&Xs[kk][ty << 2];
            float4 c = *(const float4*)&Ws[kk][tx << 2];
            acc[0][0] += a.x*c.x; acc[0][1] += a.x*c.y; acc[0][2] += a.x*c.z; acc[0][3] += a.x*c.w;
            acc[1][0] += a.y*c.x; acc[1][1] += a.y*c.y; acc[1][2] += a.y*c.z; acc[1][3] += a.y*c.w;
            acc[2][0] += a.z*c.x; acc[2][1] += a.z*c.y; acc[2][2] += a.z*c.z; acc[2][3] += a.z*c.w;
            acc[3][0] += a.w*c.x; acc[3][1] += a.w*c.y; acc[3][2] += a.w*c.z; acc[3][3] += a.w*c.w;
        }
        __syncthreads();
    }

    float4 bb = *(const float4*)(bias + bn + (tx << 2));
#pragma unroll
    for (int i = 0; i < 4; i++) {
        float4 r = make_float4(acc[i][0] + bb.x, acc[i][1] + bb.y,
                               acc[i][2] + bb.z, acc[i][3] + bb.w);
        *(float4*)(Y + (size_t)(bm + (ty << 2) + i) * N + bn + (tx << 2)) = r;
    }
}

// ---------------------------------------------------------------------------
// REVERSED-SIGN RoPE (A_rev): rotate_half(x) = concat([x2, -x1]).
// Per head, pair (j, j+32), omega_j = 10000^(-j/32):
//   x'_j      = x_j      * cos + x_{j+32} * sin
//   x'_{j+32} = x_{j+32} * cos - x_j      * sin
// Same rotation on q and k (relative). fp32 phase, double sincos.
// ---------------------------------------------------------------------------
__global__ void rope_rev(float* __restrict__ q, float* __restrict__ k)
{
    int idx = blockIdx.x * blockDim.x + threadIdx.x;
    if (idx >= BATCH * SEQ * NHEAD * 32) return;
    int j = idx & 31;
    int h = (idx >> 5) & 15;
    int s = (idx >> 9) & (SEQ - 1);
    int b = idx >> 20;

    double e = -(double)j / 32.0 * 9.210340371976184;  // -j/32 * ln(10000)
    float invf  = (float)exp(e);
    float phase = (float)s * invf;
    double cd, sd;
    sincos((double)phase, &cd, &sd);
    float c  = (float)cd;
    float sn = (float)sd;

    size_t base = ((size_t)b * SEQ + s) * D_MODEL + h * HD;
    float q1 = q[base + j], q2 = q[base + j + 32];
    q[base + j]      = q1 * c + q2 * sn;
    q[base + j + 32] = q2 * c - q1 * sn;
    float k1 = k[base + j], k2 = k[base + j + 32];
    k[base + j]      = k1 * c + k2 * sn;
    k[base + j + 32] = k2 * c - k1 * sn;
}

// ---------------------------------------------------------------------------
// Per-head flash attention, scale = HD^-0.5 = 0.125 (verified rounds 2-13).
// ---------------------------------------------------------------------------
#define SS_STRIDE 68

__global__ __launch_bounds__(256) void flash_attn(
    const float* __restrict__ Q, const float* __restrict__ K,
    const float* __restrict__ V, float* __restrict__ O)
{
    extern __shared__ float sm[];
    float* Qts = sm;
    float* KT  = sm + 4096;
    float* Vs  = sm + 8192;
    float* Ss  = sm + 12288;
    float* m_s  = Ss + 64 * SS_STRIDE;
    float* l_s  = m_s + 64;
    float* al_s = l_s + 64;

    const int tid = threadIdx.x;
    const int tx  = tid & 15;
    const int ty  = tid >> 4;
    const int qt  = blockIdx.x;
    const int h   = blockIdx.y;
    const int b   = blockIdx.z;

    const int lr  = tid >> 2;
    const int lcg = (tid & 3) << 4;

    {
        const float* qp = Q + ((size_t)(b * SEQ + qt * 64 + lr)) * D_MODEL + h * HD;
#pragma unroll
        for (int c = 0; c < 16; c += 4) {
            float4 x = *(const float4*)(qp + lcg + c);
            Qts[(lcg + c + 0) * 64 + lr] = x.x;
            Qts[(lcg + c + 1) * 64 + lr] = x.y;
            Qts[(lcg + c + 2) * 64 + lr] = x.z;
            Qts[(lcg + c + 3) * 64 + lr] = x.w;
        }
    }
    if (tid < 64) { m_s[tid] = -1e30f; l_s[tid] = 0.f; }

    float o[4][4];
#pragma unroll
    for (int i = 0; i < 4; i++)
#pragma unroll
        for (int j = 0; j < 4; j++) o[i][j] = 0.f;

    for (int kt = 0; kt < SEQ / 64; kt++) {
        __syncthreads();
        const float* kp = K + ((size_t)(b * SEQ + kt * 64 + lr)) * D_MODEL + h * HD;
        const float* vp = V + ((size_t)(b * SEQ + kt * 64 + lr)) * D_MODEL + h * HD;
#pragma unroll
        for (int c = 0; c < 16; c += 4) {
            float4 x = *(const float4*)(kp + lcg + c);
            KT[(lcg + c + 0) * 64 + lr] = x.x;
            KT[(lcg + c + 1) * 64 + lr] = x.y;
            KT[(lcg + c + 2) * 64 + lr] = x.z;
            KT[(lcg + c + 3) * 64 + lr] = x.w;
            float4 y = *(const float4*)(vp + lcg + c);
            *(float4*)&Vs[lr * 64 + lcg + c] = y;
        }
        __syncthreads();

        float sc[4][4];
#pragma unroll
        for (int i = 0; i < 4; i++)
#pragma unroll
            for (int j = 0; j < 4; j++) sc[i][j] = 0.f;

#pragma unroll 8
        for (int kk = 0; kk < 64; kk++) {
            float4 a = *(const float4*)&Qts[kk * 64 + (ty << 2)];
            float4 c = *(const float4*)&KT [kk * 64 + (tx << 2)];
            sc[0][0] += a.x*c.x; sc[0][1] += a.x*c.y; sc[0][2] += a.x*c.z; sc[0][3] += a.x*c.w;
            sc[1][0] += a.y*c.x; sc[1][1] += a.y*c.y; sc[1][2] += a.y*c.z; sc[1][3] += a.y*c.w;
            sc[2][0] += a.z*c.x; sc[2][1] += a.z*c.y; sc[2][2] += a.z*c.z; sc[2][3] += a.z*c.w;
            sc[3][0] += a.w*c.x; sc[3][1] += a.w*c.y; sc[3][2] += a.w*c.z; sc[3][3] += a.w*c.w;
        }
#pragma unroll
        for (int i = 0; i < 4; i++)
            *(float4*)&Ss[((ty << 2) + i) * SS_STRIDE + (tx << 2)] =
                make_float4(sc[i][0]*0.125f, sc[i][1]*0.125f,
                            sc[i][2]*0.125f, sc[i][3]*0.125f);
        __syncthreads();

        if (tid < 64) {
            float* row = Ss + tid * SS_STRIDE;
            float mx = -1e30f;
#pragma unroll 8
            for (int c = 0; c < 64; c++) mx = fmaxf(mx, row[c]);
            float mold = m_s[tid];
            float mnew = fmaxf(mold, mx);
            float alpha = expf(mold - mnew);
            float sum = 0.f;
#pragma unroll 8
            for (int c = 0; c < 64; c++) {
                float p = expf(row[c] - mnew);
                row[c] = p;
                sum += p;
            }
            l_s[tid]  = l_s[tid] * alpha + sum;
            m_s[tid]  = mnew;
            al_s[tid] = alpha;
        }
        __syncthreads();

#pragma unroll
        for (int i = 0; i < 4; i++) {
            float a = al_s[(ty << 2) + i];
#pragma unroll
            for (int j = 0; j < 4; j++) o[i][j] *= a;
        }
#pragma unroll 8
        for (int ss = 0; ss < 64; ss++) {
            float4 vv = *(const float4*)&Vs[ss * 64 + (tx << 2)];
            float p0 = Ss[((ty << 2) + 0) * SS_STRIDE + ss];
            float p1 = Ss[((ty << 2) + 1) * SS_STRIDE + ss];
            float p2 = Ss[((ty << 2) + 2) * SS_STRIDE + ss];
            float p3 = Ss[((ty << 2) + 3) * SS_STRIDE + ss];
            o[0][0] += p0*vv.x; o[0][1] += p0*vv.y; o[0][2] += p0*vv.z; o[0][3] += p0*vv.w;
            o[1][0] += p1*vv.x; o[1][1] += p1*vv.y; o[1][2] += p1*vv.z; o[1][3] += p1*vv.w;
            o[2][0] += p2*vv.x; o[2][1] += p2*vv.y; o[2][2] += p2*vv.z; o[2][3] += p2*vv.w;
            o[3][0] += p3*vv.x; o[3][1] += p3*vv.y; o[3][2] += p3*vv.z; o[3][3] += p3*vv.w;
        }
    }

#pragma unroll
    for (int i = 0; i < 4; i++) {
        float inv = 1.f / l_s[(ty << 2) + i];
        float4 r = make_float4(o[i][0]*inv, o[i][1]*inv, o[i][2]*inv, o[i][3]*inv);
        *(float4*)(O + ((size_t)(b * SEQ + qt * 64 + (ty << 2) + i)) * D_MODEL
                     + h * HD + (tx << 2)) = r;
    }
}

// ---------------------------------------------------------------------------
extern "C" void kernel_launch(void* const* d_in, const int* in_sizes, int n_in,
                              void* d_out, int out_size)
{
    const float* query = (const float*)d_in[0];
    const float* key_  = (const float*)d_in[1];
    const float* value = (const float*)d_in[2];
    const float* Wq = (const float*)d_in[3];  const float* bq = (const float*)d_in[4];
    const float* Wk = (const float*)d_in[5];  const float* bk = (const float*)d_in[6];
    const float* Wv = (const float*)d_in[7];  const float* bv = (const float*)d_in[8];
    const float* Wo = (const float*)d_in[9];  const float* bo = (const float*)d_in[10];
    float* out = (float*)d_out;

    float *qb, *kb, *vb, *ab;
    cudaGetSymbolAddress((void**)&qb, g_q);
    cudaGetSymbolAddress((void**)&kb, g_k);
    cudaGetSymbolAddress((void**)&vb, g_v);
    cudaGetSymbolAddress((void**)&ab, g_att);

    dim3 gg(D_MODEL / 64, MROWS / 64);   // (16, 64)

    sgemm_xwt<<<gg, 256>>>(query, Wq, bq, qb, MROWS, D_MODEL, D_MODEL);
    sgemm_xwt<<<gg, 256>>>(key_,  Wk, bk, kb, MROWS, D_MODEL, D_MODEL);
    sgemm_xwt<<<gg, 256>>>(value, Wv, bv, vb, MROWS, D_MODEL, D_MODEL);

    // Reversed-sign rotate_half RoPE (A_rev hypothesis)
    rope_rev<<<(BATCH * SEQ * NHEAD * 32 + 255) / 256, 256>>>(qb, kb);

    int smem_bytes = (12288 + 64 * SS_STRIDE + 3 * 64) * (int)sizeof(float);
    cudaFuncSetAttribute(flash_attn, cudaFuncAttributeMaxDynamicSharedMemorySize,
                         smem_bytes);
    dim3 fg(SEQ / 64, NHEAD, BATCH);     // (32, 16, 2)
    flash_attn<<<fg, 256, smem_bytes>>>(qb, kb, vb, ab);

    sgemm_xwt<<<gg, 256>>>(ab, Wo, bo, out, MROWS, D_MODEL, D_MODEL);
}

// round 16
// speedup vs baseline: 1.4333x; 1.4333x over previous
#include <cuda_runtime.h>
#include <math.h>
#include <stdint.h>

#define D_MODEL 1024
#define NHEAD   16
#define HD      64
#define BATCH   2
#define SEQ     2048
#define MROWS   (BATCH*SEQ)   // 4096

// Scratch (device globals: allocation-free per harness rules)
__device__ float g_q[MROWS*D_MODEL];
__device__ float g_k[MROWS*D_MODEL];
__device__ float g_v[MROWS*D_MODEL];
__device__ float g_att[MROWS*D_MODEL];
__device__ float g_cos[SEQ*32];
__device__ float g_sin[SEQ*32];

// ---------------------------------------------------------------------------
// tf32 helpers
// ---------------------------------------------------------------------------
__device__ __forceinline__ uint32_t f2tf32(float f) {
    uint32_t r;
    asm("cvt.rna.tf32.f32 %0, %1;" : "=r"(r) : "f"(f));
    return r;
}

__device__ __forceinline__ void mma_tf32(float* d, const uint32_t* a, const uint32_t* b) {
    asm("mma.sync.aligned.m16n8k8.row.col.f32.tf32.tf32.f32 "
        "{%0,%1,%2,%3}, {%4,%5,%6,%7}, {%8,%9}, {%0,%1,%2,%3};"
        : "+f"(d[0]), "+f"(d[1]), "+f"(d[2]), "+f"(d[3])
        : "r"(a[0]), "r"(a[1]), "r"(a[2]), "r"(a[3]), "r"(b[0]), "r"(b[1]));
}

// ---------------------------------------------------------------------------
// TF32 tensor-core GEMM: Y[m][n] = sum_k X[m][k]*W[n][k] + bias[n]
// Block 128x128x32, 256 threads (8 warps, 2m x 4n), warp tile 64x32.
// Smem k-major (Xs[k][m], Ws[k][n]) for fragment-friendly loads.
// ---------------------------------------------------------------------------
#define BM 128
#define BN 128
#define BK 32

__global__ __launch_bounds__(256) void tf32_gemm_xwt(
    const float* __restrict__ X, const float* __restrict__ W,
    const float* __restrict__ bias, float* __restrict__ Y,
    int M, int N, int K)
{
    __shared__ uint32_t Xs[BK][BM + 4];
    __shared__ uint32_t Ws[BK][BN + 4];

    const int tid  = threadIdx.x;
    const int warp = tid >> 5;
    const int lane = tid & 31;
    const int g    = lane >> 2;        // 0..7
    const int t    = lane & 3;         // 0..3
    const int wm   = (warp >> 2) * 64; // warp row offset (0 or 64)
    const int wn   = (warp & 3) * 32;  // warp col offset (0,32,64,96)

    const int bm = blockIdx.y * BM;
    const int bn = blockIdx.x * BN;

    float acc[4][4][4];
#pragma unroll
    for (int mi = 0; mi < 4; mi++)
#pragma unroll
        for (int ni = 0; ni < 4; ni++)
#pragma unroll
            for (int r = 0; r < 4; r++) acc[mi][ni][r] = 0.f;

    const int lrow = tid >> 1;            // 0..127
    const int lcol = (tid & 1) * 16;      // 0 or 16

    for (int k0 = 0; k0 < K; k0 += BK) {
        const float* xp = X + (size_t)(bm + lrow) * K + k0 + lcol;
        const float* wp = W + (size_t)(bn + lrow) * K + k0 + lcol;
#pragma unroll
        for (int i = 0; i < 4; i++) {
            float4 xv = *(const float4*)(xp + i * 4);
            Xs[lcol + i*4 + 0][lrow] = f2tf32(xv.x);
            Xs[lcol + i*4 + 1][lrow] = f2tf32(xv.y);
            Xs[lcol + i*4 + 2][lrow] = f2tf32(xv.z);
            Xs[lcol + i*4 + 3][lrow] = f2tf32(xv.w);
            float4 wv = *(const float4*)(wp + i * 4);
            Ws[lcol + i*4 + 0][lrow] = f2tf32(wv.x);
            Ws[lcol + i*4 + 1][lrow] = f2tf32(wv.y);
            Ws[lcol + i*4 + 2][lrow] = f2tf32(wv.z);
            Ws[lcol + i*4 + 3][lrow] = f2tf32(wv.w);
        }
        __syncthreads();

#pragma unroll
        for (int ks = 0; ks < BK / 8; ks++) {
            const int kk = ks * 8;
            uint32_t a[4][4], b[4][2];
#pragma unroll
            for (int mi = 0; mi < 4; mi++) {
                const int m0 = wm + mi * 16;
                a[mi][0] = Xs[kk + t    ][m0 + g];
                a[mi][1] = Xs[kk + t    ][m0 + g + 8];
                a[mi][2] = Xs[kk + t + 4][m0 + g];
                a[mi][3] = Xs[kk + t + 4][m0 + g + 8];
            }
#pragma unroll
            for (int ni = 0; ni < 4; ni++) {
                const int n0 = wn + ni * 8;
                b[ni][0] = Ws[kk + t    ][n0 + g];
                b[ni][1] = Ws[kk + t + 4][n0 + g];
            }
#pragma unroll
            for (int mi = 0; mi < 4; mi++)
#pragma unroll
                for (int ni = 0; ni < 4; ni++)
                    mma_tf32(acc[mi][ni], a[mi], b[ni]);
        }
        __syncthreads();
    }

    // Epilogue: D[g][2t],(2t+1) and D[g+8][2t],(2t+1) per mma tile, + bias
#pragma unroll
    for (int mi = 0; mi < 4; mi++) {
        const int row0 = bm + wm + mi * 16 + g;
#pragma unroll
        for (int ni = 0; ni < 4; ni++) {
            const int col = bn + wn + ni * 8 + 2 * t;
            const float b0 = bias[col], b1 = bias[col + 1];
            Y[(size_t)row0       * N + col    ] = acc[mi][ni][0] + b0;
            Y[(size_t)row0       * N + col + 1] = acc[mi][ni][1] + b1;
            Y[(size_t)(row0 + 8) * N + col    ] = acc[mi][ni][2] + b0;
            Y[(size_t)(row0 + 8) * N + col + 1] = acc[mi][ni][3] + b1;
        }
    }
}

// ---------------------------------------------------------------------------
// RoPE table: 65536 entries (s, j). DP sincos ONCE per unique angle.
// ---------------------------------------------------------------------------
__global__ void rope_table(float* __restrict__ ct, float* __restrict__ st)
{
    int idx = blockIdx.x * blockDim.x + threadIdx.x;
    if (idx >= SEQ * 32) return;
    int j = idx & 31;
    int s = idx >> 5;
    double e = -(double)j / 32.0 * 9.210340371976184;  // -j/32 * ln(10000)
    float invf  = (float)exp(e);
    float phase = (float)s * invf;                     // fp32 phase
    double cd, sd;
    sincos((double)phase, &cd, &sd);
    ct[idx] = (float)cd;
    st[idx] = (float)sd;
}

// ---------------------------------------------------------------------------
// REVERSED-SIGN RoPE apply (A_rev, VERIFIED round 15):
//   x'_j      = x_j      * cos + x_{j+32} * sin
//   x'_{j+32} = x_{j+32} * cos - x_j      * sin
// ---------------------------------------------------------------------------
__global__ void rope_apply(float* __restrict__ q, float* __restrict__ k,
                           const float* __restrict__ ct, const float* __restrict__ st)
{
    int idx = blockIdx.x * blockDim.x + threadIdx.x;
    if (idx >= BATCH * SEQ * NHEAD * 32) return;
    int j = idx & 31;
    int h = (idx >> 5) & 15;
    int s = (idx >> 9) & (SEQ - 1);
    int b = idx >> 20;

    float c  = ct[s * 32 + j];
    float sn = st[s * 32 + j];

    size_t base = ((size_t)b * SEQ + s) * D_MODEL + h * HD;
    float q1 = q[base + j], q2 = q[base + j + 32];
    q[base + j]      = q1 * c + q2 * sn;
    q[base + j + 32] = q2 * c - q1 * sn;
    float k1 = k[base + j], k2 = k[base + j + 32];
    k[base + j]      = k1 * c + k2 * sn;
    k[base + j + 32] = k2 * c - k1 * sn;
}

// ---------------------------------------------------------------------------
// Per-head flash attention, scale = HD^-0.5 = 0.125 (VERIFIED round 15).
// ---------------------------------------------------------------------------
#define SS_STRIDE 68

__global__ __launch_bounds__(256) void flash_attn(
    const float* __restrict__ Q, const float* __restrict__ K,
    const float* __restrict__ V, float* __restrict__ O)
{
    extern __shared__ float sm[];
    float* Qts = sm;
    float* KT  = sm + 4096;
    float* Vs  = sm + 8192;
    float* Ss  = sm + 12288;
    float* m_s  = Ss + 64 * SS_STRIDE;
    float* l_s  = m_s + 64;
    float* al_s = l_s + 64;

    const int tid = threadIdx.x;
    const int tx  = tid & 15;
    const int ty  = tid >> 4;
    const int qt  = blockIdx.x;
    const int h   = blockIdx.y;
    const int b   = blockIdx.z;

    const int lr  = tid >> 2;
    const int lcg = (tid & 3) << 4;

    {
        const float* qp = Q + ((size_t)(b * SEQ + qt * 64 + lr)) * D_MODEL + h * HD;
#pragma unroll
        for (int c = 0; c < 16; c += 4) {
            float4 x = *(const float4*)(qp + lcg + c);
            Qts[(lcg + c + 0) * 64 + lr] = x.x;
            Qts[(lcg + c + 1) * 64 + lr] = x.y;
            Qts[(lcg + c + 2) * 64 + lr] = x.z;
            Qts[(lcg + c + 3) * 64 + lr] = x.w;
        }
    }
    if (tid < 64) { m_s[tid] = -1e30f; l_s[tid] = 0.f; }

    float o[4][4];
#pragma unroll
    for (int i = 0; i < 4; i++)
#pragma unroll
        for (int j = 0; j < 4; j++) o[i][j] = 0.f;

    for (int kt = 0; kt < SEQ / 64; kt++) {
        __syncthreads();
        const float* kp = K + ((size_t)(b * SEQ + kt * 64 + lr)) * D_MODEL + h * HD;
        const float* vp = V + ((size_t)(b * SEQ + kt * 64 + lr)) * D_MODEL + h * HD;
#pragma unroll
        for (int c = 0; c < 16; c += 4) {
            float4 x = *(const float4*)(kp + lcg + c);
            KT[(lcg + c + 0) * 64 + lr] = x.x;
            KT[(lcg + c + 1) * 64 + lr] = x.y;
            KT[(lcg + c + 2) * 64 + lr] = x.z;
            KT[(lcg + c + 3) * 64 + lr] = x.w;
            float4 y = *(const float4*)(vp + lcg + c);
            *(float4*)&Vs[lr * 64 + lcg + c] = y;
        }
        __syncthreads();

        float sc[4][4];
#pragma unroll
        for (int i = 0; i < 4; i++)
#pragma unroll
            for (int j = 0; j < 4; j++) sc[i][j] = 0.f;

#pragma unroll 8
        for (int kk = 0; kk < 64; kk++) {
            float4 a = *(const float4*)&Qts[kk * 64 + (ty << 2)];
            float4 c = *(const float4*)&KT [kk * 64 + (tx << 2)];
            sc[0][0] += a.x*c.x; sc[0][1] += a.x*c.y; sc[0][2] += a.x*c.z; sc[0][3] += a.x*c.w;
            sc[1][0] += a.y*c.x; sc[1][1] += a.y*c.y; sc[1][2] += a.y*c.z; sc[1][3] += a.y*c.w;
            sc[2][0] += a.z*c.x; sc[2][1] += a.z*c.y; sc[2][2] += a.z*c.z; sc[2][3] += a.z*c.w;
            sc[3][0] += a.w*c.x; sc[3][1] += a.w*c.y; sc[3][2] += a.w*c.z; sc[3][3] += a.w*c.w;
        }
#pragma unroll
        for (int i = 0; i < 4; i++)
            *(float4*)&Ss[((ty << 2) + i) * SS_STRIDE + (tx << 2)] =
                make_float4(sc[i][0]*0.125f, sc[i][1]*0.125f,
                            sc[i][2]*0.125f, sc[i][3]*0.125f);
        __syncthreads();

        if (tid < 64) {
            float* row = Ss + tid * SS_STRIDE;
            float mx = -1e30f;
#pragma unroll 8
            for (int c = 0; c < 64; c++) mx = fmaxf(mx, row[c]);
            float mold = m_s[tid];
            float mnew = fmaxf(mold, mx);
            float alpha = expf(mold - mnew);
            float sum = 0.f;
#pragma unroll 8
            for (int c = 0; c < 64; c++) {
                float p = expf(row[c] - mnew);
                row[c] = p;
                sum += p;
            }
            l_s[tid]  = l_s[tid] * alpha + sum;
            m_s[tid]  = mnew;
            al_s[tid] = alpha;
        }
        __syncthreads();

#pragma unroll
        for (int i = 0; i < 4; i++) {
            float a = al_s[(ty << 2) + i];
#pragma unroll
            for (int j = 0; j < 4; j++) o[i][j] *= a;
        }
#pragma unroll 8
        for (int ss = 0; ss < 64; ss++) {
            float4 vv = *(const float4*)&Vs[ss * 64 + (tx << 2)];
            float p0 = Ss[((ty << 2) + 0) * SS_STRIDE + ss];
            float p1 = Ss[((ty << 2) + 1) * SS_STRIDE + ss];
            float p2 = Ss[((ty << 2) + 2) * SS_STRIDE + ss];
            float p3 = Ss[((ty << 2) + 3) * SS_STRIDE + ss];
            o[0][0] += p0*vv.x; o[0][1] += p0*vv.y; o[0][2] += p0*vv.z; o[0][3] += p0*vv.w;
            o[1][0] += p1*vv.x; o[1][1] += p1*vv.y; o[1][2] += p1*vv.z; o[1][3] += p1*vv.w;
            o[2][0] += p2*vv.x; o[2][1] += p2*vv.y; o[2][2] += p2*vv.z; o[2][3] += p2*vv.w;
            o[3][0] += p3*vv.x; o[3][1] += p3*vv.y; o[3][2] += p3*vv.z; o[3][3] += p3*vv.w;
        }
    }

#pragma unroll
    for (int i = 0; i < 4; i++) {
        float inv = 1.f / l_s[(ty << 2) + i];
        float4 r = make_float4(o[i][0]*inv, o[i][1]*inv, o[i][2]*inv, o[i][3]*inv);
        *(float4*)(O + ((size_t)(b * SEQ + qt * 64 + (ty << 2) + i)) * D_MODEL
                     + h * HD + (tx << 2)) = r;
    }
}

// ---------------------------------------------------------------------------
extern "C" void kernel_launch(void* const* d_in, const int* in_sizes, int n_in,
                              void* d_out, int out_size)
{
    const float* query = (const float*)d_in[0];
    const float* key_  = (const float*)d_in[1];
    const float* value = (const float*)d_in[2];
    const float* Wq = (const float*)d_in[3];  const float* bq = (const float*)d_in[4];
    const float* Wk = (const float*)d_in[5];  const float* bk = (const float*)d_in[6];
    const float* Wv = (const float*)d_in[7];  const float* bv = (const float*)d_in[8];
    const float* Wo = (const float*)d_in[9];  const float* bo = (const float*)d_in[10];
    float* out = (float*)d_out;

    float *qb, *kb, *vb, *ab, *ct, *st;
    cudaGetSymbolAddress((void**)&qb, g_q);
    cudaGetSymbolAddress((void**)&kb, g_k);
    cudaGetSymbolAddress((void**)&vb, g_v);
    cudaGetSymbolAddress((void**)&ab, g_att);
    cudaGetSymbolAddress((void**)&ct, g_cos);
    cudaGetSymbolAddress((void**)&st, g_sin);

    dim3 gg(D_MODEL / BN, MROWS / BM);   // (8, 32)

    tf32_gemm_xwt<<<gg, 256>>>(query, Wq, bq, qb, MROWS, D_MODEL, D_MODEL);
    tf32_gemm_xwt<<<gg, 256>>>(key_,  Wk, bk, kb, MROWS, D_MODEL, D_MODEL);
    tf32_gemm_xwt<<<gg, 256>>>(value, Wv, bv, vb, MROWS, D_MODEL, D_MODEL);

    rope_table<<<(SEQ * 32 + 255) / 256, 256>>>(ct, st);
    rope_apply<<<(BATCH * SEQ * NHEAD * 32 + 255) / 256, 256>>>(qb, kb, ct, st);

    int smem_bytes = (12288 + 64 * SS_STRIDE + 3 * 64) * (int)sizeof(float);
    cudaFuncSetAttribute(flash_attn, cudaFuncAttributeMaxDynamicSharedMemorySize,
                         smem_bytes);
    dim3 fg(SEQ / 64, NHEAD, BATCH);     // (32, 16, 2)
    flash_attn<<<fg, 256, smem_bytes>>>(qb, kb, vb, ab);

    tf32_gemm_xwt<<<gg, 256>>>(ab, Wo, bo, out, MROWS, D_MODEL, D_MODEL);
}

// round 17
// speedup vs baseline: 1.8864x; 1.3162x over previous
#include <cuda_runtime.h>
#include <math.h>
#include <stdint.h>

#define D_MODEL 1024
#define NHEAD   16
#define HD      64
#define BATCH   2
#define SEQ     2048
#define MROWS   (BATCH*SEQ)   // 4096

// Scratch (device globals: allocation-free per harness rules)
__device__ float g_q[MROWS*D_MODEL];
__device__ float g_k[MROWS*D_MODEL];
__device__ float g_v[MROWS*D_MODEL];
__device__ float g_att[MROWS*D_MODEL];
__device__ float g_cos[SEQ*32];
__device__ float g_sin[SEQ*32];

// ---------------------------------------------------------------------------
// tf32 helpers (verified round 16)
// ---------------------------------------------------------------------------
__device__ __forceinline__ uint32_t f2tf32(float f) {
    uint32_t r;
    asm("cvt.rna.tf32.f32 %0, %1;" : "=r"(r) : "f"(f));
    return r;
}

__device__ __forceinline__ void mma_tf32(float* d, const uint32_t* a, const uint32_t* b) {
    asm("mma.sync.aligned.m16n8k8.row.col.f32.tf32.tf32.f32 "
        "{%0,%1,%2,%3}, {%4,%5,%6,%7}, {%8,%9}, {%0,%1,%2,%3};"
        : "+f"(d[0]), "+f"(d[1]), "+f"(d[2]), "+f"(d[3])
        : "r"(a[0]), "r"(a[1]), "r"(a[2]), "r"(a[3]), "r"(b[0]), "r"(b[1]));
}

// ---------------------------------------------------------------------------
// TF32 tensor-core GEMM (VERIFIED round 16): Y = X @ W^T + bias
// ---------------------------------------------------------------------------
#define BM 128
#define BN 128
#define BK 32

__global__ __launch_bounds__(256) void tf32_gemm_xwt(
    const float* __restrict__ X, const float* __restrict__ W,
    const float* __restrict__ bias, float* __restrict__ Y,
    int M, int N, int K)
{
    __shared__ uint32_t Xs[BK][BM + 4];
    __shared__ uint32_t Ws[BK][BN + 4];

    const int tid  = threadIdx.x;
    const int warp = tid >> 5;
    const int lane = tid & 31;
    const int g    = lane >> 2;
    const int t    = lane & 3;
    const int wm   = (warp >> 2) * 64;
    const int wn   = (warp & 3) * 32;

    const int bm = blockIdx.y * BM;
    const int bn = blockIdx.x * BN;

    float acc[4][4][4];
#pragma unroll
    for (int mi = 0; mi < 4; mi++)
#pragma unroll
        for (int ni = 0; ni < 4; ni++)
#pragma unroll
            for (int r = 0; r < 4; r++) acc[mi][ni][r] = 0.f;

    const int lrow = tid >> 1;
    const int lcol = (tid & 1) * 16;

    for (int k0 = 0; k0 < K; k0 += BK) {
        const float* xp = X + (size_t)(bm + lrow) * K + k0 + lcol;
        const float* wp = W + (size_t)(bn + lrow) * K + k0 + lcol;
#pragma unroll
        for (int i = 0; i < 4; i++) {
            float4 xv = *(const float4*)(xp + i * 4);
            Xs[lcol + i*4 + 0][lrow] = f2tf32(xv.x);
            Xs[lcol + i*4 + 1][lrow] = f2tf32(xv.y);
            Xs[lcol + i*4 + 2][lrow] = f2tf32(xv.z);
            Xs[lcol + i*4 + 3][lrow] = f2tf32(xv.w);
            float4 wv = *(const float4*)(wp + i * 4);
            Ws[lcol + i*4 + 0][lrow] = f2tf32(wv.x);
            Ws[lcol + i*4 + 1][lrow] = f2tf32(wv.y);
            Ws[lcol + i*4 + 2][lrow] = f2tf32(wv.z);
            Ws[lcol + i*4 + 3][lrow] = f2tf32(wv.w);
        }
        __syncthreads();

#pragma unroll
        for (int ks = 0; ks < BK / 8; ks++) {
            const int kk = ks * 8;
            uint32_t a[4][4], b[4][2];
#pragma unroll
            for (int mi = 0; mi < 4; mi++) {
                const int m0 = wm + mi * 16;
                a[mi][0] = Xs[kk + t    ][m0 + g];
                a[mi][1] = Xs[kk + t    ][m0 + g + 8];
                a[mi][2] = Xs[kk + t + 4][m0 + g];
                a[mi][3] = Xs[kk + t + 4][m0 + g + 8];
            }
#pragma unroll
            for (int ni = 0; ni < 4; ni++) {
                const int n0 = wn + ni * 8;
                b[ni][0] = Ws[kk + t    ][n0 + g];
                b[ni][1] = Ws[kk + t + 4][n0 + g];
            }
#pragma unroll
            for (int mi = 0; mi < 4; mi++)
#pragma unroll
                for (int ni = 0; ni < 4; ni++)
                    mma_tf32(acc[mi][ni], a[mi], b[ni]);
        }
        __syncthreads();
    }

#pragma unroll
    for (int mi = 0; mi < 4; mi++) {
        const int row0 = bm + wm + mi * 16 + g;
#pragma unroll
        for (int ni = 0; ni < 4; ni++) {
            const int col = bn + wn + ni * 8 + 2 * t;
            const float b0 = bias[col], b1 = bias[col + 1];
            Y[(size_t)row0       * N + col    ] = acc[mi][ni][0] + b0;
            Y[(size_t)row0       * N + col + 1] = acc[mi][ni][1] + b1;
            Y[(size_t)(row0 + 8) * N + col    ] = acc[mi][ni][2] + b0;
            Y[(size_t)(row0 + 8) * N + col + 1] = acc[mi][ni][3] + b1;
        }
    }
}

// ---------------------------------------------------------------------------
// RoPE table + reversed-sign apply (VERIFIED rounds 15/16)
// ---------------------------------------------------------------------------
__global__ void rope_table(float* __restrict__ ct, float* __restrict__ st)
{
    int idx = blockIdx.x * blockDim.x + threadIdx.x;
    if (idx >= SEQ * 32) return;
    int j = idx & 31;
    int s = idx >> 5;
    double e = -(double)j / 32.0 * 9.210340371976184;
    float invf  = (float)exp(e);
    float phase = (float)s * invf;
    double cd, sd;
    sincos((double)phase, &cd, &sd);
    ct[idx] = (float)cd;
    st[idx] = (float)sd;
}

__global__ void rope_apply(float* __restrict__ q, float* __restrict__ k,
                           const float* __restrict__ ct, const float* __restrict__ st)
{
    int idx = blockIdx.x * blockDim.x + threadIdx.x;
    if (idx >= BATCH * SEQ * NHEAD * 32) return;
    int j = idx & 31;
    int h = (idx >> 5) & 15;
    int s = (idx >> 9) & (SEQ - 1);
    int b = idx >> 20;

    float c  = ct[s * 32 + j];
    float sn = st[s * 32 + j];

    size_t base = ((size_t)b * SEQ + s) * D_MODEL + h * HD;
    float q1 = q[base + j], q2 = q[base + j + 32];
    q[base + j]      = q1 * c + q2 * sn;
    q[base + j + 32] = q2 * c - q1 * sn;
    float k1 = k[base + j], k2 = k[base + j + 32];
    k[base + j]      = k1 * c + k2 * sn;
    k[base + j + 32] = k2 * c - k1 * sn;
}

// ---------------------------------------------------------------------------
// Tensor-core flash attention (tf32), scale = 0.125.
// Block = (b, h, 64-query tile), 128 threads = 4 warps, warp = 16 query rows.
// S = Q K^T via mma (Qs,Ks k-major smem); softmax in registers (xor shuffles
// across the 4 t-lanes per row); P staged through warp-private smem (P^T,
// key-major) to form A-fragments; O += P V via mma (Vs natural = B layout).
// ---------------------------------------------------------------------------
#define FAS 68   // smem row stride

__global__ __launch_bounds__(128) void flash_attn_tc(
    const float* __restrict__ Q, const float* __restrict__ K,
    const float* __restrict__ V, float* __restrict__ Out)
{
    extern __shared__ uint32_t smu[];
    uint32_t* Qs = smu;                 // [64][FAS]  Q^T (dim-major)
    uint32_t* Ks = smu + 64 * FAS;      // [64][FAS]  K^T (dim-major)
    uint32_t* Vs = smu + 2 * 64 * FAS;  // [64][FAS]  V (key-major)
    uint32_t* Ps = smu + 3 * 64 * FAS;  // [64][FAS]  P^T (key-major)

    const int tid  = threadIdx.x;
    const int warp = tid >> 5;
    const int lane = tid & 31;
    const int g    = lane >> 2;        // 0..7
    const int t    = lane & 3;         // 0..3
    const int wm   = warp * 16;        // warp's query-row offset

    const int qt = blockIdx.x;
    const int h  = blockIdx.y;
    const int b  = blockIdx.z;

    const int lr  = tid >> 1;          // 0..63 (row to load)
    const int seg = (tid & 1) * 32;    // column segment {0,32}

    // Load Q tile: transpose + tf32
    {
        const float* qp = Q + ((size_t)(b * SEQ + qt * 64 + lr)) * D_MODEL + h * HD;
#pragma unroll
        for (int c = 0; c < 32; c += 4) {
            float4 x = *(const float4*)(qp + seg + c);
            Qs[(seg + c + 0) * FAS + lr] = f2tf32(x.x);
            Qs[(seg + c + 1) * FAS + lr] = f2tf32(x.y);
            Qs[(seg + c + 2) * FAS + lr] = f2tf32(x.z);
            Qs[(seg + c + 3) * FAS + lr] = f2tf32(x.w);
        }
    }

    float m0 = -1e30f, m1 = -1e30f, l0 = 0.f, l1 = 0.f;
    float o[8][4];
#pragma unroll
    for (int ni = 0; ni < 8; ni++)
#pragma unroll
        for (int r = 0; r < 4; r++) o[ni][r] = 0.f;

    for (int kt = 0; kt < SEQ / 64; kt++) {
        __syncthreads();   // prior-tile Ks/Vs consumers done; Qs stores done (1st iter)
        const float* kp = K + ((size_t)(b * SEQ + kt * 64 + lr)) * D_MODEL + h * HD;
        const float* vp = V + ((size_t)(b * SEQ + kt * 64 + lr)) * D_MODEL + h * HD;
#pragma unroll
        for (int c = 0; c < 32; c += 4) {
            float4 x = *(const float4*)(kp + seg + c);
            Ks[(seg + c + 0) * FAS + lr] = f2tf32(x.x);
            Ks[(seg + c + 1) * FAS + lr] = f2tf32(x.y);
            Ks[(seg + c + 2) * FAS + lr] = f2tf32(x.z);
            Ks[(seg + c + 3) * FAS + lr] = f2tf32(x.w);
            float4 y = *(const float4*)(vp + seg + c);
            Vs[lr * FAS + seg + c + 0] = f2tf32(y.x);
            Vs[lr * FAS + seg + c + 1] = f2tf32(y.y);
            Vs[lr * FAS + seg + c + 2] = f2tf32(y.z);
            Vs[lr * FAS + seg + c + 3] = f2tf32(y.w);
        }
        __syncthreads();

        // ---- S = Q K^T (8 k-steps over dims, 8 n-tiles over keys) ----
        float s[8][4];
#pragma unroll
        for (int ni = 0; ni < 8; ni++)
#pragma unroll
            for (int r = 0; r < 4; r++) s[ni][r] = 0.f;

#pragma unroll
        for (int ks = 0; ks < 8; ks++) {
            const int kk = ks * 8;
            uint32_t a[4];
            a[0] = Qs[(kk + t    ) * FAS + wm + g];
            a[1] = Qs[(kk + t    ) * FAS + wm + g + 8];
            a[2] = Qs[(kk + t + 4) * FAS + wm + g];
            a[3] = Qs[(kk + t + 4) * FAS + wm + g + 8];
#pragma unroll
            for (int ni = 0; ni < 8; ni++) {
                uint32_t bb[2];
                bb[0] = Ks[(kk + t    ) * FAS + ni * 8 + g];
                bb[1] = Ks[(kk + t + 4) * FAS + ni * 8 + g];
                mma_tf32(s[ni], a, bb);
            }
        }

        // ---- online softmax (rows g and g+8; 4 t-lanes co-own each row) ----
        float mx0 = -1e30f, mx1 = -1e30f;
#pragma unroll
        for (int ni = 0; ni < 8; ni++) {
            s[ni][0] *= 0.125f; s[ni][1] *= 0.125f;
            s[ni][2] *= 0.125f; s[ni][3] *= 0.125f;
            mx0 = fmaxf(mx0, fmaxf(s[ni][0], s[ni][1]));
            mx1 = fmaxf(mx1, fmaxf(s[ni][2], s[ni][3]));
        }
        mx0 = fmaxf(mx0, __shfl_xor_sync(0xffffffffu, mx0, 1));
        mx0 = fmaxf(mx0, __shfl_xor_sync(0xffffffffu, mx0, 2));
        mx1 = fmaxf(mx1, __shfl_xor_sync(0xffffffffu, mx1, 1));
        mx1 = fmaxf(mx1, __shfl_xor_sync(0xffffffffu, mx1, 2));

        float mn0 = fmaxf(m0, mx0), mn1 = fmaxf(m1, mx1);
        float al0 = expf(m0 - mn0), al1 = expf(m1 - mn1);
        float sum0 = 0.f, sum1 = 0.f;
#pragma unroll
        for (int ni = 0; ni < 8; ni++) {
            s[ni][0] = expf(s[ni][0] - mn0);
            s[ni][1] = expf(s[ni][1] - mn0);
            s[ni][2] = expf(s[ni][2] - mn1);
            s[ni][3] = expf(s[ni][3] - mn1);
            sum0 += s[ni][0] + s[ni][1];
            sum1 += s[ni][2] + s[ni][3];
        }
        sum0 += __shfl_xor_sync(0xffffffffu, sum0, 1);
        sum0 += __shfl_xor_sync(0xffffffffu, sum0, 2);
        sum1 += __shfl_xor_sync(0xffffffffu, sum1, 1);
        sum1 += __shfl_xor_sync(0xffffffffu, sum1, 2);

        l0 = l0 * al0 + sum0;  m0 = mn0;
        l1 = l1 * al1 + sum1;  m1 = mn1;

#pragma unroll
        for (int ni = 0; ni < 8; ni++) {
            o[ni][0] *= al0; o[ni][1] *= al0;
            o[ni][2] *= al1; o[ni][3] *= al1;
        }

        // ---- stage P^T (key-major, warp-private columns) ----
#pragma unroll
        for (int ni = 0; ni < 8; ni++) {
            Ps[(ni * 8 + 2*t    ) * FAS + wm + g    ] = f2tf32(s[ni][0]);
            Ps[(ni * 8 + 2*t + 1) * FAS + wm + g    ] = f2tf32(s[ni][1]);
            Ps[(ni * 8 + 2*t    ) * FAS + wm + g + 8] = f2tf32(s[ni][2]);
            Ps[(ni * 8 + 2*t + 1) * FAS + wm + g + 8] = f2tf32(s[ni][3]);
        }
        __syncwarp();

        // ---- O += P V (8 k-steps over keys, 8 n-tiles over dims) ----
#pragma unroll
        for (int ks = 0; ks < 8; ks++) {
            const int kk = ks * 8;
            uint32_t a[4];
            a[0] = Ps[(kk + t    ) * FAS + wm + g];
            a[1] = Ps[(kk + t    ) * FAS + wm + g + 8];
            a[2] = Ps[(kk + t + 4) * FAS + wm + g];
            a[3] = Ps[(kk + t + 4) * FAS + wm + g + 8];
#pragma unroll
            for (int ni = 0; ni < 8; ni++) {
                uint32_t bb[2];
                bb[0] = Vs[(kk + t    ) * FAS + ni * 8 + g];
                bb[1] = Vs[(kk + t + 4) * FAS + ni * 8 + g];
                mma_tf32(o[ni], a, bb);
            }
        }
    }

    // ---- normalize and write out ----
    const float inv0 = 1.f / l0, inv1 = 1.f / l1;
    const size_t row0 = (size_t)(b * SEQ + qt * 64 + wm + g);
#pragma unroll
    for (int ni = 0; ni < 8; ni++) {
        float2 r0 = make_float2(o[ni][0] * inv0, o[ni][1] * inv0);
        *(float2*)(Out + row0 * D_MODEL + h * HD + ni * 8 + 2 * t) = r0;
        float2 r1 = make_float2(o[ni][2] * inv1, o[ni][3] * inv1);
        *(float2*)(Out + (row0 + 8) * D_MODEL + h * HD + ni * 8 + 2 * t) = r1;
    }
}

// ---------------------------------------------------------------------------
extern "C" void kernel_launch(void* const* d_in, const int* in_sizes, int n_in,
                              void* d_out, int out_size)
{
    const float* query = (const float*)d_in[0];
    const float* key_  = (const float*)d_in[1];
    const float* value = (const float*)d_in[2];
    const float* Wq = (const float*)d_in[3];  const float* bq = (const float*)d_in[4];
    const float* Wk = (const float*)d_in[5];  const float* bk = (const float*)d_in[6];
    const float* Wv = (const float*)d_in[7];  const float* bv = (const float*)d_in[8];
    const float* Wo = (const float*)d_in[9];  const float* bo = (const float*)d_in[10];
    float* out = (float*)d_out;

    float *qb, *kb, *vb, *ab, *ct, *st;
    cudaGetSymbolAddress((void**)&qb, g_q);
    cudaGetSymbolAddress((void**)&kb, g_k);
    cudaGetSymbolAddress((void**)&vb, g_v);
    cudaGetSymbolAddress((void**)&ab, g_att);
    cudaGetSymbolAddress((void**)&ct, g_cos);
    cudaGetSymbolAddress((void**)&st, g_sin);

    dim3 gg(D_MODEL / BN, MROWS / BM);   // (8, 32)

    tf32_gemm_xwt<<<gg, 256>>>(query, Wq, bq, qb, MROWS, D_MODEL, D_MODEL);
    tf32_gemm_xwt<<<gg, 256>>>(key_,  Wk, bk, kb, MROWS, D_MODEL, D_MODEL);
    tf32_gemm_xwt<<<gg, 256>>>(value, Wv, bv, vb, MROWS, D_MODEL, D_MODEL);

    rope_table<<<(SEQ * 32 + 255) / 256, 256>>>(ct, st);
    rope_apply<<<(BATCH * SEQ * NHEAD * 32 + 255) / 256, 256>>>(qb, kb, ct, st);

    int fa_smem = 4 * 64 * FAS * (int)sizeof(uint32_t);  // 69632 B
    cudaFuncSetAttribute(flash_attn_tc, cudaFuncAttributeMaxDynamicSharedMemorySize,
                         fa_smem);
    dim3 fg(SEQ / 64, NHEAD, BATCH);     // (32, 16, 2)
    flash_attn_tc<<<fg, 128, fa_smem>>>(qb, kb, vb, ab);

    tf32_gemm_xwt<<<gg, 256>>>(ab, Wo, bo, out, MROWS, D_MODEL, D_MODEL);
}